// round 4
// baseline (speedup 1.0000x reference)
#include <cuda_runtime.h>
#include <cuda_bf16.h>
#include <cstdint>

// GraphSage_89781996355909 — exact algebraic collapse (see R1 analysis).
//
// Final reference op: jax.nn.softmax(x @ W5 + b5, axis=-1) with last-axis
// dim 1 (W5: [8,1]). Single-element softmax == 1.0 for any finite logit, and
// all upstream values are finite, so output == ones(512) for ALL inputs.
//
// R4: single-warp specialization for the known out_size=512. One CTA, 32
// threads, 4 unrolled STG.128 per thread (128 total = 2 KB), zero bounds
// checks, zero predication. Generic fallback kept for any other out_size.

__global__ void __launch_bounds__(32, 1)
GraphSage_89781996355909_fill512(float4* __restrict__ out4) {
    const float4 ones = make_float4(1.0f, 1.0f, 1.0f, 1.0f);
    int t = threadIdx.x;            // 0..31
#pragma unroll
    for (int j = 0; j < 4; ++j)
        out4[t + 32 * j] = ones;    // covers 128 float4 = 512 floats
}

__global__ void GraphSage_89781996355909_fill1(float* __restrict__ out, int n) {
    int i = threadIdx.x + blockIdx.x * blockDim.x;
    if (i < n) out[i] = 1.0f;
}

extern "C" void kernel_launch(void* const* d_in, const int* in_sizes, int n_in,
                              void* d_out, int out_size) {
    (void)d_in; (void)in_sizes; (void)n_in;
    if (out_size == 512 && (((unsigned long long)d_out) & 15ull) == 0) {
        GraphSage_89781996355909_fill512<<<1, 32>>>((float4*)d_out);
    } else {
        int threads = 256;
        int blocks = (out_size + threads - 1) / threads;
        if (blocks < 1) blocks = 1;
        GraphSage_89781996355909_fill1<<<blocks, threads>>>((float*)d_out, out_size);
    }
}

// round 5
// speedup vs baseline: 1.0559x; 1.0559x over previous
#include <cuda_runtime.h>
#include <cuda_bf16.h>
#include <cstdint>

// GraphSage_89781996355909 — exact algebraic collapse (see R1 analysis).
//
// Final reference op: jax.nn.softmax(x @ W5 + b5, axis=-1) with last-axis
// dim 1 (W5: [8,1]). Single-element softmax == 1.0 for any finite logit, and
// all upstream values are finite, so output == ones(512) for ALL inputs.
//
// FINAL (R3 config, confirmed fastest): single CTA, 128 threads, one STG.128
// per thread (128 float4 = 512 floats). Four warps issue stores across all
// four SMSPs in parallel — measured faster than both the 2-CTA scalar fill
// (R1: 6.9us) and the single-warp unrolled variant (R4: 4.8us). Remaining
// time is graph-replay + launch floor (DRAM/issue ~0% in ncu).
// Scalar fallback kept for any other out_size/alignment.

__global__ void GraphSage_89781996355909_fill4(float4* __restrict__ out4, int n4) {
    int i = threadIdx.x + blockIdx.x * blockDim.x;
    if (i < n4) out4[i] = make_float4(1.0f, 1.0f, 1.0f, 1.0f);
}

__global__ void GraphSage_89781996355909_fill1(float* __restrict__ out, int n) {
    int i = threadIdx.x + blockIdx.x * blockDim.x;
    if (i < n) out[i] = 1.0f;
}

extern "C" void kernel_launch(void* const* d_in, const int* in_sizes, int n_in,
                              void* d_out, int out_size) {
    (void)d_in; (void)in_sizes; (void)n_in;
    if ((out_size & 3) == 0 && (((unsigned long long)d_out) & 15ull) == 0) {
        int n4 = out_size >> 2;              // 512 -> 128
        int threads = (n4 < 128) ? (n4 > 0 ? n4 : 1) : 128;
        int blocks = (n4 + threads - 1) / threads;
        if (blocks < 1) blocks = 1;
        GraphSage_89781996355909_fill4<<<blocks, threads>>>((float4*)d_out, n4);
    } else {
        int threads = 256;
        int blocks = (out_size + threads - 1) / threads;
        if (blocks < 1) blocks = 1;
        GraphSage_89781996355909_fill1<<<blocks, threads>>>((float*)d_out, out_size);
    }
}